// round 1
// baseline (speedup 1.0000x reference)
#include <cuda_runtime.h>

// Problem constants
#define Bb 32
#define Cc 256
#define Ss 1024      // H*W
#define Nn 32768     // B*H*W tokens
#define Dd 256       // embedding dim
#define Kk 1024      // codebook size

// Output layout: concat(out[B,C,H,W], loss, entropy, encodings[N,K])
#define OUT_Q    0
#define OUT_LOSS 8388608
#define OUT_ENT  8388609
#define OUT_ENC  8388610

typedef unsigned long long u64;

// Scratch (device globals: no allocations allowed)
__device__ float g_wnorm[Kk];
__device__ float g_xnorm[Nn];
__device__ float g_dmin[Nn];
__device__ int   g_idx[Nn];
__device__ int   g_cnt[Kk];

__device__ __forceinline__ u64 pack2(float lo, float hi){
  u64 r; asm("mov.b64 %0, {%1, %2};" : "=l"(r) : "f"(lo), "f"(hi)); return r;
}
__device__ __forceinline__ void unpack2(u64 v, float &lo, float &hi){
  asm("mov.b64 {%0, %1}, %2;" : "=f"(lo), "=f"(hi) : "l"(v));
}
// Blackwell packed fp32 FMA: 2 MACs per instruction
__device__ __forceinline__ void fma2(u64 &d, u64 a, u64 b){
  asm("fma.rn.f32x2 %0, %1, %2, %0;" : "+l"(d) : "l"(a), "l"(b));
}

__global__ void vq_init(){ g_cnt[threadIdx.x] = 0; }

// ||w_k||^2, one warp per row
__global__ void vq_wnorm(const float* __restrict__ W){
  int r = blockIdx.x * 8 + (threadIdx.x >> 5);
  int lane = threadIdx.x & 31;
  const float4* w4 = (const float4*)(W + r * Dd);
  float4 a = w4[lane], b = w4[lane + 32];
  float s = a.x*a.x + a.y*a.y + a.z*a.z + a.w*a.w
          + b.x*b.x + b.y*b.y + b.z*b.z + b.w*b.w;
  #pragma unroll
  for (int o = 16; o > 0; o >>= 1) s += __shfl_xor_sync(0xffffffffu, s, o);
  if (lane == 0) g_wnorm[r] = s;
}

// Fused distance GEMM + argmin.
// X viewed as [B][D][S] (d-contiguous tokens), W is [K][D].
// Block: 128 tokens x 256 codes, D-chunks of 16.
// Thread (tx 0..15, ty 0..15): 8 tokens (4 f32x2 pairs) x 16 codes.
#define TM  128
#define TKC 256
#define TD  16

__global__ __launch_bounds__(256, 1) void vq_gemm(const float* __restrict__ X,
                                                  const float* __restrict__ W){
  __shared__ __align__(16) float As[TD][TM];
  __shared__ __align__(16) float Wt[TD][TKC + 4];
  __shared__ u64 red[TM];

  const int t  = threadIdx.x;
  const int tx = t & 15, ty = t >> 4;
  const int n0 = blockIdx.x * TM;
  const float* Xb = X + (n0 >> 10) * (Cc * Ss) + (n0 & (Ss - 1));

  float minv[8]; int mini[8];
  #pragma unroll
  for (int i = 0; i < 8; i++){ minv[i] = 3.4e38f; mini[i] = 0; }
  u64 xn[4] = {0ull, 0ull, 0ull, 0ull};

  for (int kc = 0; kc < Kk / TKC; kc++){
    u64 acc[4][16];
    #pragma unroll
    for (int ip = 0; ip < 4; ip++)
      #pragma unroll
      for (int j = 0; j < 16; j++) acc[ip][j] = 0ull;

    float4 pa[2], pw[4];
    // preload D-chunk 0 into registers
    {
      #pragma unroll
      for (int i = 0; i < 2; i++){ int id = i*256 + t; int d = id >> 5, s4 = id & 31;
        pa[i] = *(const float4*)(Xb + d * Ss + s4 * 4); }
      #pragma unroll
      for (int i = 0; i < 4; i++){ int id = i*256 + t; int k = id >> 2, dd = id & 3;
        pw[i] = *(const float4*)(W + (kc*TKC + k) * Dd + dd * 4); }
    }

    for (int dc = 0; dc < Dd / TD; dc++){
      // stage regs -> smem
      #pragma unroll
      for (int i = 0; i < 2; i++){ int id = i*256 + t; int d = id >> 5, s4 = id & 31;
        *(float4*)&As[d][s4 * 4] = pa[i]; }
      #pragma unroll
      for (int i = 0; i < 4; i++){ int id = i*256 + t; int k = id >> 2, dd = id & 3;
        Wt[dd*4+0][k] = pw[i].x; Wt[dd*4+1][k] = pw[i].y;
        Wt[dd*4+2][k] = pw[i].z; Wt[dd*4+3][k] = pw[i].w; }
      __syncthreads();

      // prefetch next D-chunk while computing this one
      if (dc + 1 < Dd / TD){
        const int d0 = (dc + 1) * TD;
        #pragma unroll
        for (int i = 0; i < 2; i++){ int id = i*256 + t; int d = id >> 5, s4 = id & 31;
          pa[i] = *(const float4*)(Xb + (d0 + d) * Ss + s4 * 4); }
        #pragma unroll
        for (int i = 0; i < 4; i++){ int id = i*256 + t; int k = id >> 2, dd = id & 3;
          pw[i] = *(const float4*)(W + (kc*TKC + k) * Dd + d0 + dd * 4); }
      }

      #pragma unroll 4
      for (int d = 0; d < TD; d++){
        u64 ap[4];
        const u64* arow = (const u64*)&As[d][0];
        #pragma unroll
        for (int ip = 0; ip < 4; ip++) ap[ip] = arow[ty * 4 + ip];
        if (kc == 0){
          #pragma unroll
          for (int ip = 0; ip < 4; ip++) fma2(xn[ip], ap[ip], ap[ip]);
        }
        #pragma unroll
        for (int jj = 0; jj < 4; jj++){
          float4 b4 = *(const float4*)&Wt[d][jj * 64 + tx * 4];
          u64 b2;
          b2 = pack2(b4.x, b4.x);
          #pragma unroll
          for (int ip = 0; ip < 4; ip++) fma2(acc[ip][jj*4+0], ap[ip], b2);
          b2 = pack2(b4.y, b4.y);
          #pragma unroll
          for (int ip = 0; ip < 4; ip++) fma2(acc[ip][jj*4+1], ap[ip], b2);
          b2 = pack2(b4.z, b4.z);
          #pragma unroll
          for (int ip = 0; ip < 4; ip++) fma2(acc[ip][jj*4+2], ap[ip], b2);
          b2 = pack2(b4.w, b4.w);
          #pragma unroll
          for (int ip = 0; ip < 4; ip++) fma2(acc[ip][jj*4+3], ap[ip], b2);
        }
      }
      __syncthreads();
    }

    if (kc == 0 && tx == 0){
      #pragma unroll
      for (int ip = 0; ip < 4; ip++){
        float lo, hi; unpack2(xn[ip], lo, hi);
        g_xnorm[n0 + ty*8 + ip*2 + 0] = lo;
        g_xnorm[n0 + ty*8 + ip*2 + 1] = hi;
      }
    }

    // per-thread argmin update, k strictly ascending (matches jnp first-min tiebreak)
    #pragma unroll
    for (int jj = 0; jj < 4; jj++)
      #pragma unroll
      for (int q = 0; q < 4; q++){
        int k = kc * TKC + jj * 64 + tx * 4 + q;
        float wn = g_wnorm[k];
        #pragma unroll
        for (int ip = 0; ip < 4; ip++){
          float lo, hi; unpack2(acc[ip][jj*4 + q], lo, hi);
          float v0 = wn - 2.0f * lo;
          float v1 = wn - 2.0f * hi;
          if (v0 < minv[ip*2+0]) { minv[ip*2+0] = v0; mini[ip*2+0] = k; }
          if (v1 < minv[ip*2+1]) { minv[ip*2+1] = v1; mini[ip*2+1] = k; }
        }
      }
  }

  // block-level argmin reduce: packed (orderable float, idx), smaller idx wins ties
  if (t < TM) red[t] = 0xFFFFFFFFFFFFFFFFull;
  __syncthreads();
  #pragma unroll
  for (int i = 0; i < 8; i++){
    unsigned u = __float_as_uint(minv[i]);
    u = (u & 0x80000000u) ? ~u : (u | 0x80000000u);
    u64 key = ((u64)u << 32) | (unsigned)mini[i];
    atomicMin(&red[ty * 8 + i], key);
  }
  __syncthreads();
  if (t < TM){
    u64 key = red[t];
    unsigned u  = (unsigned)(key >> 32);
    unsigned fb = (u & 0x80000000u) ? (u & 0x7fffffffu) : ~u;
    g_dmin[n0 + t] = __uint_as_float(fb);
    int id = (int)(key & 0xffffffffu);
    g_idx[n0 + t] = id;
    atomicAdd(&g_cnt[id], 1);
  }
}

// quantized output in BCHW: out[b][c][s] = W[idx[b*1024+s]][c]
__global__ void vq_gather(const float* __restrict__ W, float* __restrict__ out){
  int g   = blockIdx.x * 256 + threadIdx.x;   // N*D/4 threads
  int c4  = g >> 15;                          // 0..63
  int rem = g & 32767;                        // token n
  int b = rem >> 10, s = rem & 1023;
  int id = g_idx[rem];
  float4 w = *(const float4*)(W + id * Dd + c4 * 4);
  float* o = out + b * (Cc * Ss) + (c4 * 4) * Ss + s;
  o[0] = w.x; o[Ss] = w.y; o[2*Ss] = w.z; o[3*Ss] = w.w;
}

// one-hot encodings, float2 stores (base only 8B-aligned)
__global__ void vq_enc(float* __restrict__ enc){
  int g  = blockIdx.x * 256 + threadIdx.x;    // N*K/2 threads
  int n  = g >> 9;
  int k2 = (g & 511) * 2;
  int id = g_idx[n];
  float2 v;
  v.x = (id == k2    ) ? 1.0f : 0.0f;
  v.y = (id == k2 + 1) ? 1.0f : 0.0f;
  *(float2*)(enc + (size_t)n * Kk + k2) = v;
}

// deterministic loss + entropy (single block, fixed reduction trees)
__global__ void vq_final(float* __restrict__ scal){
  __shared__ float sh[1024];
  int t = threadIdx.x;
  float s = 0.0f;
  for (int i = t; i < Nn; i += 1024) s += g_xnorm[i] + g_dmin[i];
  sh[t] = s; __syncthreads();
  for (int o = 512; o > 0; o >>= 1){ if (t < o) sh[t] += sh[t + o]; __syncthreads(); }
  float losssum = sh[0];
  __syncthreads();
  float p = (float)g_cnt[t] * (1.0f / (float)Nn);
  sh[t] = -p * logf(p + 1e-10f);
  __syncthreads();
  for (int o = 512; o > 0; o >>= 1){ if (t < o) sh[t] += sh[t + o]; __syncthreads(); }
  if (t == 0){
    scal[0] = 0.25f * losssum / (float)(Nn * Dd);  // COMMIT * e_latent_loss
    scal[1] = sh[0];                               // vq_entropy
  }
}

extern "C" void kernel_launch(void* const* d_in, const int* in_sizes, int n_in,
                              void* d_out, int out_size){
  (void)in_sizes; (void)n_in; (void)out_size;
  const float* X = (const float*)d_in[0];   // inputs [B,C,H,W] f32
  const float* W = (const float*)d_in[1];   // codebook [K,D] f32
  float* out = (float*)d_out;

  vq_init  <<<1, Kk>>>();
  vq_wnorm <<<Kk / 8, 256>>>(W);
  vq_gemm  <<<Nn / TM, 256>>>(X, W);
  vq_gather<<<(Nn * Dd / 4) / 256, 256>>>(W, out + OUT_Q);
  vq_enc   <<<(Nn * (Kk / 2)) / 256, 256>>>(out + OUT_ENC);
  vq_final <<<1, Kk>>>(out + OUT_LOSS);
}